// round 15
// baseline (speedup 1.0000x reference)
#include <cuda_runtime.h>
#include <cuda_bf16.h>
#include <math.h>

#define BB 32
#define TT 24
#define NN 1024
#define NCTA 512
#define NTHR 128
#define GRP 16                 // CTAs per batch
#define ROWS 64                // rows per CTA

// ---------------- fp32 scratch ----------------
#define OFF_AX   0                          // 3 groups x (B,N,16) = A@x_t
#define OFF_RS   (3 * BB * NN * 16)         // (B,N) rowsum(A)
#define OFF_TVF  (OFF_RS + BB * NN)         // (B,2)
#define SCRATCH_FLOATS (OFF_TVF + BB * 2)

__device__ float d_scratch[SCRATCH_FLOATS];
// A bf16 packed in mma-fragment order: per CTA 8192 uint4 (128KB)
__device__ uint4 d_Apk[(size_t)NCTA * 8192];
__device__ __nv_bfloat16 d_xbf[(size_t)BB * 48 * NN];   // X^T: 0-15 h1, 16-31 h2, 32-47 r*h
__device__ __nv_bfloat16 d_xt [(size_t)BB * 48 * NN];   // gathered x_t, transposed
__device__ unsigned g_bcnt[BB * 32];
__device__ volatile unsigned g_bgen[BB * 32];

// dynamic smem (words): X 16 x 516 | stage 64 x 17
#define XPW 516
#define SPW 17
#define SW_X   0
#define SW_STG 8256
#define SMEM_WORDS (SW_STG + ROWS * SPW)
#define DSMEM_BYTES (SMEM_WORDS * 4)

__device__ __forceinline__ float sigf(float x) { return 1.0f / (1.0f + expf(-x)); }

__device__ __forceinline__ void cpa16s(unsigned* sm, const void* gm) {
    unsigned sa = (unsigned)__cvta_generic_to_shared(sm);
    asm volatile("cp.async.cg.shared.global [%0], [%1], 16;" :: "r"(sa), "l"(gm) : "memory");
}
#define CP_COMMIT() asm volatile("cp.async.commit_group;" ::: "memory")
#define CP_WAIT(n)  asm volatile("cp.async.wait_group %0;" :: "n"(n) : "memory")

__device__ __forceinline__ unsigned long long dup2(float x) {
    unsigned long long r; unsigned u = __float_as_uint(x);
    asm("mov.b64 %0, {%1, %1};" : "=l"(r) : "r"(u));
    return r;
}
__device__ __forceinline__ void fma2(unsigned long long& s, unsigned long long a, unsigned long long w) {
    asm("fma.rn.f32x2 %0, %1, %2, %0;" : "+l"(s) : "l"(a), "l"(w));
}
__device__ __forceinline__ void unpack2(unsigned long long s, float& x, float& y) {
    unsigned lo, hi; asm("mov.b64 {%0, %1}, %2;" : "=r"(lo), "=r"(hi) : "l"(s));
    x = __uint_as_float(lo); y = __uint_as_float(hi);
}
__device__ __forceinline__ unsigned packbf2(float2 v) {
    __nv_bfloat162 b = __float22bfloat162_rn(v);
    return *(unsigned*)&b;
}

// per-batch barrier (R7-R14 proven), GRP CTAs per batch
__device__ __forceinline__ void batchbar(int b) {
    __threadfence();
    __syncthreads();
    if (threadIdx.x == 0) {
        unsigned gen = g_bgen[b * 32];
        if (atomicAdd(&g_bcnt[b * 32], 1) == GRP - 1) {
            g_bcnt[b * 32] = 0;
            __threadfence();
            g_bgen[b * 32] = gen + 1;
        } else {
            while (g_bgen[b * 32] == gen) __nanosleep(32);
        }
        __threadfence();
    }
    __syncthreads();
}

// ---------- GEMM phase (C=16): acc[64 rows x 16]; warp w owns rows w*16..w*16+15 ----------
__device__ void gemmL(const uint4* __restrict__ Apk,
                      const __nv_bfloat16* __restrict__ Xb,
                      unsigned* smem_u, float acc[2][4]) {
    const int tid = threadIdx.x, w = tid >> 5, lane = tid & 31;
    unsigned* Xs = smem_u + SW_X;

    __syncthreads();               // prior phase finished reading Xs/stage
#pragma unroll
    for (int q = 0; q < 16; q++) {
        int i = tid + q * NTHR;
        int c = i >> 7, ch = i & 127;
        cpa16s(Xs + c * XPW + ch * 4, Xb + (size_t)c * NN + ch * 8);
    }
    CP_COMMIT();
    CP_WAIT(0);
    __syncthreads();

#pragma unroll
    for (int nt = 0; nt < 2; nt++)
#pragma unroll
        for (int q = 0; q < 4; q++) acc[nt][q] = 0.f;

    const unsigned xB = (unsigned)__cvta_generic_to_shared(Xs);
    const unsigned boff = ((unsigned)(lane & 7) * XPW + ((lane >> 3) & 1) * 4) * 4;
    const uint4* Aw = Apk + (size_t)w * 64 * 32 + lane;

    uint4 r0[4];
#pragma unroll
    for (int p = 0; p < 4; p++) r0[p] = Aw[p * 32];

    for (int kb = 0; kb < 16; kb++) {
#pragma unroll
        for (int q = 0; q < 4; q++) {
            const int ks = kb * 4 + q;
            unsigned bf[2][2];
#pragma unroll
            for (int nt = 0; nt < 2; nt++) {
                unsigned ad = xB + boff + (unsigned)nt * 8 * XPW * 4 + (unsigned)ks * 32;
                asm volatile("ldmatrix.sync.aligned.m8n8.x2.shared.b16 {%0,%1}, [%2];"
                             : "=r"(bf[nt][0]), "=r"(bf[nt][1]) : "r"(ad));
            }
            uint4 fa = r0[q];
            if (kb < 15) r0[q] = Aw[(ks + 4) * 32];
#pragma unroll
            for (int nt = 0; nt < 2; nt++) {
                asm volatile(
                    "mma.sync.aligned.m16n8k16.row.col.f32.bf16.bf16.f32 "
                    "{%0,%1,%2,%3},{%4,%5,%6,%7},{%8,%9},{%0,%1,%2,%3};"
                    : "+f"(acc[nt][0]), "+f"(acc[nt][1]), "+f"(acc[nt][2]), "+f"(acc[nt][3])
                    : "r"(fa.x), "r"(fa.y), "r"(fa.z), "r"(fa.w),
                      "r"(bf[nt][0]), "r"(bf[nt][1]));
            }
        }
    }
}

// scatter acc to stage (64 rows, pitch 17); caller syncs and reads rows
__device__ __forceinline__ void toStage(unsigned* smem_u, const float acc[2][4]) {
    float* stage = (float*)(smem_u + SW_STG);
    const int tid = threadIdx.x, w = tid >> 5, lane = tid & 31;
    const int g = lane >> 2, c2 = (lane & 3) * 2;
    const int rr = w * 16 + g;
#pragma unroll
    for (int nt = 0; nt < 2; nt++) {
        int col = nt * 8 + c2;
        stage[rr * SPW + col]           = acc[nt][0];
        stage[rr * SPW + col + 1]       = acc[nt][1];
        stage[(rr + 8) * SPW + col]     = acc[nt][2];
        stage[(rr + 8) * SPW + col + 1] = acc[nt][3];
    }
    __syncthreads();
}

// ================= persistent kernel =================
__global__ void __launch_bounds__(NTHR, 4) persistK(
    const float* __restrict__ A, const float* __restrict__ recent,
    const float* __restrict__ g1rW, const float* __restrict__ g1rb,
    const float* __restrict__ g1uW, const float* __restrict__ g1ub,
    const float* __restrict__ g1cW, const float* __restrict__ g1cb,
    const float* __restrict__ g2rW, const float* __restrict__ g2rb,
    const float* __restrict__ g2uW, const float* __restrict__ g2ub,
    const float* __restrict__ g2cW, const float* __restrict__ g2cb,
    const float* __restrict__ gcnW, const float* __restrict__ gcnb,
    float* __restrict__ out) {
    extern __shared__ __align__(16) unsigned smem_u[];
    __shared__ __align__(16) float tabs[2530];
    float* stage = (float*)(smem_u + SW_STG);

    const int tid = threadIdx.x, w = tid >> 5, lane = tid & 31;
    const int b = blockIdx.x >> 4, rb = blockIdx.x & 15;
    const int row0 = rb * ROWS;
    const int row = tid & 63, jh = tid >> 6, j0 = jh * 8;
    const int n0 = row0 + row;
    const size_t r0 = (size_t)b * NN + n0;

    // ---- weight tables into static smem ----
    {
        float2* W1 = (float2*)(tabs + 0);
        for (int i = tid; i < 288; i += NTHR) W1[i] = make_float2(g1rW[i], g1uW[i]);
        float2* W2 = (float2*)(tabs + 576);
        for (int i = tid; i < 512; i += NTHR) W2[i] = make_float2(g2rW[i], g2uW[i]);
        float2* C1 = (float2*)(tabs + 1600);
        for (int i = tid; i < 144; i += NTHR) {
            int k = i >> 3, m = i & 7;
            C1[i] = make_float2(g1cW[(2 * m) * 18 + k], g1cW[(2 * m + 1) * 18 + k]);
        }
        float2* C2 = (float2*)(tabs + 1888);
        for (int i = tid; i < 256; i += NTHR) {
            int k = i >> 3, m = i & 7;
            C2[i] = make_float2(g2cW[(2 * m) * 32 + k], g2cW[(2 * m + 1) * 32 + k]);
        }
        if (tid < 16) ((float2*)(tabs + 2400))[tid] = make_float2(g1rb[tid], g1ub[tid]);
        else if (tid < 32) ((float2*)(tabs + 2432))[tid - 16] = make_float2(g2rb[tid - 16], g2ub[tid - 16]);
        else if (tid < 40) ((float2*)(tabs + 2464))[tid - 32] = make_float2(g1cb[2 * (tid - 32)], g1cb[2 * (tid - 32) + 1]);
        else if (tid < 48) ((float2*)(tabs + 2480))[tid - 40] = make_float2(g2cb[2 * (tid - 40)], g2cb[2 * (tid - 40) + 1]);
        else if (tid < 80) { int i = tid - 48; tabs[2496 + i] = gcnW[(i >> 4) * 80 + (i & 15)]; }
        else if (tid < 82) tabs[2528 + tid - 80] = gcnb[tid - 80];
    }

    // ---- pack own A slice (64 rows) into mma-fragment order + fused rowsum ----
    const float* Arow = A + ((size_t)b * NN + row0) * NN;
    uint4* pk = d_Apk + (size_t)blockIdx.x * 8192;
    {
        const int gr = lane >> 2, k0b = (lane & 3) * 2;
        const int blk = w;                           // 4 warps, 4 blocks
        const int rowbase = blk * 16;
        const float* rp0 = Arow + (size_t)(rowbase + gr) * NN;
        const float* rp8 = Arow + (size_t)(rowbase + gr + 8) * NN;
        float s0 = 0.f, s8 = 0.f;
        for (int ks = 0; ks < 64; ks++) {
            int k0 = ks * 16 + k0b;
            float2 a0 = *(const float2*)(rp0 + k0);
            float2 a8 = *(const float2*)(rp8 + k0);
            float2 b0 = *(const float2*)(rp0 + k0 + 8);
            float2 b8 = *(const float2*)(rp8 + k0 + 8);
            s0 += (a0.x + a0.y) + (b0.x + b0.y);
            s8 += (a8.x + a8.y) + (b8.x + b8.y);
            uint4 u;
            u.x = packbf2(a0); u.y = packbf2(a8); u.z = packbf2(b0); u.w = packbf2(b8);
            pk[((size_t)blk * 64 + ks) * 32 + lane] = u;
        }
#pragma unroll
        for (int o = 1; o < 4; o <<= 1) {
            s0 += __shfl_xor_sync(~0u, s0, o);
            s8 += __shfl_xor_sync(~0u, s8, o);
        }
        if ((lane & 3) == 0) {
            d_scratch[OFF_RS + (size_t)b * NN + row0 + rowbase + gr]     = s0;
            d_scratch[OFF_RS + (size_t)b * NN + row0 + rowbase + gr + 8] = s8;
        }
    }

    // ---- gather x_t (transposed bf16, t-range split by jh) + zero h columns ----
    {
        const float2* rp = (const float2*)recent;
        for (int t = jh * 12; t < jh * 12 + 12; t++) {
            float2 v = rp[(size_t)(b * TT + t) * NN + n0];
            d_xt[((size_t)b * 48 + 2 * t) * NN + n0]     = __float2bfloat16_rn(v.x);
            d_xt[((size_t)b * 48 + 2 * t + 1) * NN + n0] = __float2bfloat16_rn(v.y);
        }
        __nv_bfloat16 z = __float2bfloat16_rn(0.f);
        for (int c = jh * 16; c < jh * 16 + 16; c++) d_xbf[((size_t)b * 48 + c) * NN + n0] = z;
    }

    float h1[8], h2[8], uu[8], ah1[16], ah2[16];
#pragma unroll
    for (int k = 0; k < 8; k++) { h1[k] = 0.f; h2[k] = 0.f; }
#pragma unroll
    for (int k = 0; k < 16; k++) { ah1[k] = 0.f; ah2[k] = 0.f; }
    float acc[2][4];

    batchbar(b);

    // ---- de-phase the 32 batch pipelines: deterministic per-batch skew ----
    // Identical programs start phase-locked -> gemm bursts and idle windows
    // align chip-wide, capping LTS at ~50% duty. Skew batches across ~1 phase.
    {
        unsigned long long tgt = clock64() + (unsigned long long)(((b * 7) & 15) * 1200);
        while (clock64() < tgt) {}
    }

    // ---- A @ x_t for all 24 timesteps (CTA-local outputs) ----
    for (int g = 0; g < 3; g++) {
        gemmL(pk, d_xt + ((size_t)b * 48 + g * 16) * NN, smem_u, acc);
        toStage(smem_u, acc);
        float* axp = d_scratch + OFF_AX + (size_t)g * (BB * NN * 16) + r0 * 16 + jh * 8;
        const float* srow = stage + row * SPW + jh * 8;
        ((float4*)axp)[0] = make_float4(srow[0], srow[1], srow[2], srow[3]);
        ((float4*)axp)[1] = make_float4(srow[4], srow[5], srow[6], srow[7]);
    }

    const __nv_bfloat16* xbB = d_xbf + (size_t)b * 48 * NN;
    __nv_bfloat16* xo_h1 = d_xbf + ((size_t)b * 48 + 0) * NN + n0;
    __nv_bfloat16* xo_h2 = d_xbf + ((size_t)b * 48 + 16) * NN + n0;
    __nv_bfloat16* xo_rh = d_xbf + ((size_t)b * 48 + 32) * NN + n0;

    const unsigned long long* W1ru = (const unsigned long long*)(tabs + 0);
    const unsigned long long* W2ru = (const unsigned long long*)(tabs + 576);
    const unsigned long long* W1cp = (const unsigned long long*)(tabs + 1600);
    const unsigned long long* W2cp = (const unsigned long long*)(tabs + 1888);
    const unsigned long long* B1ru = (const unsigned long long*)(tabs + 2400);
    const unsigned long long* B2ru = (const unsigned long long*)(tabs + 2432);
    const unsigned long long* B1cp = (const unsigned long long*)(tabs + 2464);
    const unsigned long long* B2cp = (const unsigned long long*)(tabs + 2480);

    for (int t = 0; t < TT; t++) {
        const int g = t >> 3, p = t & 7;
        const float* axp = d_scratch + OFF_AX + (size_t)g * (BB * NN * 16) + r0 * 16 + p * 2;
        float2 axv = *(const float2*)axp;

        // ---- gates1: [ax | ah1(regs)] -> uu, r1*h1 (no gemm) ----
        {
            float xh[18];
            xh[0] = axv.x; xh[1] = axv.y;
#pragma unroll
            for (int k = 0; k < 16; k++) xh[2 + k] = ah1[k];
#pragma unroll
            for (int jj = 0; jj < 8; jj++) {
                const int j = j0 + jj;
                unsigned long long s = B1ru[j];
#pragma unroll
                for (int k = 0; k < 18; k++) fma2(s, dup2(xh[k]), W1ru[j * 18 + k]);
                float sr, su; unpack2(s, sr, su);
                uu[jj] = sigf(su);
                xo_rh[(size_t)j * NN] = __float2bfloat16_rn(sigf(sr) * h1[jj]);
            }
        }
        batchbar(b);

        // ---- G1: A@(r1*h1); gates2 -> h1' ----
        {
            gemmL(pk, xbB + (size_t)32 * NN, smem_u, acc);
            toStage(smem_u, acc);
            const float* srow = stage + row * SPW;
            float xh[18];
            xh[0] = axv.x; xh[1] = axv.y;
#pragma unroll
            for (int k = 0; k < 16; k++) xh[2 + k] = srow[k];
            unsigned long long sm[4];
#pragma unroll
            for (int m = 0; m < 4; m++) sm[m] = B1cp[jh * 4 + m];
#pragma unroll
            for (int k = 0; k < 18; k++) {
                unsigned long long a = dup2(xh[k]);
#pragma unroll
                for (int m = 0; m < 4; m++) fma2(sm[m], a, W1cp[k * 8 + jh * 4 + m]);
            }
#pragma unroll
            for (int m = 0; m < 4; m++) {
                float c0, c1; unpack2(sm[m], c0, c1);
                int jj = 2 * m;
                h1[jj]     = uu[jj]     * h1[jj]     + (1.f - uu[jj])     * tanhf(c0);
                h1[jj + 1] = uu[jj + 1] * h1[jj + 1] + (1.f - uu[jj + 1]) * tanhf(c1);
                xo_h1[(size_t)(j0 + jj) * NN]     = __float2bfloat16_rn(h1[jj]);
                xo_h1[(size_t)(j0 + jj + 1) * NN] = __float2bfloat16_rn(h1[jj + 1]);
            }
        }
        batchbar(b);

        // ---- G2: A@h1' -> ah1 (persist); gates3 -> uu, r2*h2 ----
        {
            gemmL(pk, xbB, smem_u, acc);
            toStage(smem_u, acc);
            const float* srow = stage + row * SPW;
#pragma unroll
            for (int k = 0; k < 16; k++) ah1[k] = srow[k];
#pragma unroll
            for (int jj = 0; jj < 8; jj++) {
                const int j = j0 + jj;
                unsigned long long s = B2ru[j];
#pragma unroll
                for (int k = 0; k < 16; k++) fma2(s, dup2(ah1[k]), W2ru[j * 32 + k]);
#pragma unroll
                for (int k = 0; k < 16; k++) fma2(s, dup2(ah2[k]), W2ru[j * 32 + 16 + k]);
                float sr, su; unpack2(s, sr, su);
                uu[jj] = sigf(su);
                xo_rh[(size_t)j * NN] = __float2bfloat16_rn(sigf(sr) * h2[jj]);
            }
        }
        batchbar(b);

        // ---- G3: A@(r2*h2); gates4 -> h2' ----
        {
            gemmL(pk, xbB + (size_t)32 * NN, smem_u, acc);
            toStage(smem_u, acc);
            const float* srow = stage + row * SPW;
            unsigned long long sm[4];
#pragma unroll
            for (int m = 0; m < 4; m++) sm[m] = B2cp[jh * 4 + m];
#pragma unroll
            for (int k = 0; k < 16; k++) {
                unsigned long long a = dup2(ah1[k]);
#pragma unroll
                for (int m = 0; m < 4; m++) fma2(sm[m], a, W2cp[k * 8 + jh * 4 + m]);
            }
#pragma unroll
            for (int k = 0; k < 16; k++) {
                unsigned long long a = dup2(srow[k]);
#pragma unroll
                for (int m = 0; m < 4; m++) fma2(sm[m], a, W2cp[(16 + k) * 8 + jh * 4 + m]);
            }
#pragma unroll
            for (int m = 0; m < 4; m++) {
                float c0, c1; unpack2(sm[m], c0, c1);
                int jj = 2 * m;
                h2[jj]     = uu[jj]     * h2[jj]     + (1.f - uu[jj])     * tanhf(c0);
                h2[jj + 1] = uu[jj + 1] * h2[jj + 1] + (1.f - uu[jj + 1]) * tanhf(c1);
                xo_h2[(size_t)(j0 + jj) * NN]     = __float2bfloat16_rn(h2[jj]);
                xo_h2[(size_t)(j0 + jj + 1) * NN] = __float2bfloat16_rn(h2[jj + 1]);
            }
        }
        batchbar(b);

        // ---- G4: A@h2' -> ah2 (persist; feeds next gates3 + final GCN) ----
        gemmL(pk, xbB + (size_t)16 * NN, smem_u, acc);
        toStage(smem_u, acc);
        {
            const float* srow = stage + row * SPW;
#pragma unroll
            for (int k = 0; k < 16; k++) ah2[k] = srow[k];
        }
        // no barrier: next write (gates1 -> rh cols 32-47) doesn't alias cols 16-31,
        // and the batchbar after gates1 precedes the next gemm read.
    }

    // ---- final: ah2 (= A@h2 final) + folded trend/feat, tanh ----
    if (jh == 0) {
        float rs = d_scratch[OFF_RS + r0];
        float o0 = tabs[2528] + rs * d_scratch[OFF_TVF + b * 2];
        float o1 = tabs[2529] + rs * d_scratch[OFF_TVF + b * 2 + 1];
#pragma unroll
        for (int c = 0; c < 16; c++) {
            o0 += ah2[c] * tabs[2496 + c];
            o1 += ah2[c] * tabs[2496 + 16 + c];
        }
        *(float2*)(out + r0 * 2) = make_float2(tanhf(o0), tanhf(o1));
    }
}

// ---- 2-layer LSTM + feat FF folded into tvf (B,2) ----
__global__ __launch_bounds__(1024) void prepK(
    const float* __restrict__ trend, const float* __restrict__ tf,
    const float* __restrict__ Wih0, const float* __restrict__ Whh0,
    const float* __restrict__ bih0, const float* __restrict__ bhh0,
    const float* __restrict__ Wih1, const float* __restrict__ Whh1,
    const float* __restrict__ bih1, const float* __restrict__ bhh1,
    const float* __restrict__ ffW, const float* __restrict__ ffb,
    const float* __restrict__ gcnW) {
    __shared__ float h1s[32][32], c1s[32][32], h2s[32][32], c2s[32][32], feats[32][32];
    int tid = threadIdx.x;
    int b = tid >> 5, j = tid & 31;
    h1s[b][j] = 0.f; c1s[b][j] = 0.f; h2s[b][j] = 0.f; c2s[b][j] = 0.f;
    __syncthreads();

    for (int t = 0; t < TT; t++) {
        float x0 = trend[(b * TT + t) * 2 + 0];
        float x1 = trend[(b * TT + t) * 2 + 1];
        float g0[4];
#pragma unroll
        for (int g = 0; g < 4; g++) {
            int idx = g * 32 + j;
            float s = bih0[idx] + bhh0[idx] + Wih0[idx * 2] * x0 + Wih0[idx * 2 + 1] * x1;
            for (int k = 0; k < 32; k++) s += Whh0[idx * 32 + k] * h1s[b][k];
            g0[g] = s;
        }
        float c1 = sigf(g0[1]) * c1s[b][j] + sigf(g0[0]) * tanhf(g0[2]);
        float h1 = sigf(g0[3]) * tanhf(c1);
        __syncthreads();
        h1s[b][j] = h1; c1s[b][j] = c1;
        __syncthreads();

        float g1[4];
#pragma unroll
        for (int g = 0; g < 4; g++) {
            int idx = g * 32 + j;
            float s = bih1[idx] + bhh1[idx];
            for (int k = 0; k < 32; k++)
                s += Wih1[idx * 32 + k] * h1s[b][k] + Whh1[idx * 32 + k] * h2s[b][k];
            g1[g] = s;
        }
        float c2 = sigf(g1[1]) * c2s[b][j] + sigf(g1[0]) * tanhf(g1[2]);
        float h2 = sigf(g1[3]) * tanhf(c2);
        __syncthreads();
        h2s[b][j] = h2; c2s[b][j] = c2;
        __syncthreads();
    }

    float s = ffb[j];
    for (int k = 0; k < 31; k++) s += tf[b * 31 + k] * ffW[j * 31 + k];
    feats[b][j] = fmaxf(s, 0.f);
    __syncthreads();

    if (tid < 64) {
        int bb = tid >> 1, f = tid & 1;
        float s2 = 0.f;
        for (int c = 0; c < 32; c++)
            s2 += h2s[bb][c] * gcnW[f * 80 + 16 + c] + feats[bb][c] * gcnW[f * 80 + 48 + c];
        d_scratch[OFF_TVF + bb * 2 + f] = s2;
    }
}

// ================================== launcher ===================================
extern "C" void kernel_launch(void* const* d_in, const int* in_sizes, int n_in,
                              void* d_out, int out_size) {
    const float* recent = (const float*)d_in[0];
    const float* trend  = (const float*)d_in[1];
    const float* A      = (const float*)d_in[2];
    const float* tf     = (const float*)d_in[3];
    const float* g1rW = (const float*)d_in[4],  *g1rb = (const float*)d_in[5];
    const float* g1uW = (const float*)d_in[6],  *g1ub = (const float*)d_in[7];
    const float* g1cW = (const float*)d_in[8],  *g1cb = (const float*)d_in[9];
    const float* g2rW = (const float*)d_in[10], *g2rb = (const float*)d_in[11];
    const float* g2uW = (const float*)d_in[12], *g2ub = (const float*)d_in[13];
    const float* g2cW = (const float*)d_in[14], *g2cb = (const float*)d_in[15];
    const float* Wih0 = (const float*)d_in[16], *Whh0 = (const float*)d_in[17];
    const float* bih0 = (const float*)d_in[18], *bhh0 = (const float*)d_in[19];
    const float* Wih1 = (const float*)d_in[20], *Whh1 = (const float*)d_in[21];
    const float* bih1 = (const float*)d_in[22], *bhh1 = (const float*)d_in[23];
    const float* ffW  = (const float*)d_in[24], *ffb  = (const float*)d_in[25];
    const float* gcnW = (const float*)d_in[26], *gcnb = (const float*)d_in[27];
    float* out = (float*)d_out;

    cudaFuncSetAttribute(persistK, cudaFuncAttributeMaxDynamicSharedMemorySize, DSMEM_BYTES);

    prepK<<<1, 1024>>>(trend, tf, Wih0, Whh0, bih0, bhh0,
                       Wih1, Whh1, bih1, bhh1, ffW, ffb, gcnW);
    persistK<<<NCTA, NTHR, DSMEM_BYTES>>>(A, recent,
                                          g1rW, g1rb, g1uW, g1ub, g1cW, g1cb,
                                          g2rW, g2rb, g2uW, g2ub, g2cW, g2cb,
                                          gcnW, gcnb, out);
}

// round 16
// speedup vs baseline: 1.0191x; 1.0191x over previous
#include <cuda_runtime.h>
#include <cuda_bf16.h>
#include <cuda_fp8.h>
#include <math.h>

#define BB 32
#define TT 24
#define NN 1024
#define NCTA 512
#define NTHR 128
#define GRP 16                 // CTAs per batch
#define ROWS 64                // rows per CTA

#define SCA 131072.f           // A scale (2^17): A*SCA in (0,1]
#define SCX 16.f               // X scale (2^4)
#define OSC (1.f / 2097152.f)  // output unscale (2^-21)

// ---------------- fp32 scratch ----------------
#define OFF_AX   0                          // 3 groups x (B,N,16) = A@x_t
#define OFF_RS   (3 * BB * NN * 16)         // (B,N) rowsum(A)
#define OFF_TVF  (OFF_RS + BB * NN)         // (B,2)
#define SCRATCH_FLOATS (OFF_TVF + BB * 2)

__device__ float d_scratch[SCRATCH_FLOATS];
// A e4m3 packed in mma-fragment order: per CTA 4096 uint4 (64KB)
// index: ((blk*32 + ks)*32 + lane), blk = 16-row block 0..3, ks = k32 step
__device__ uint4 d_Apk[(size_t)NCTA * 4096];
__device__ unsigned char d_xbf[(size_t)BB * 48 * NN];   // X^T fp8: 0-15 h1, 16-31 h2, 32-47 r*h
__device__ unsigned char d_xt [(size_t)BB * 48 * NN];   // gathered x_t fp8, transposed
__device__ unsigned g_bcnt[BB * 32];
__device__ volatile unsigned g_bgen[BB * 32];

// dynamic smem: X fp8 16 x 1040 B | stage 64 x 17 fp32
#define XPB 1040
#define SPW 17
#define SW_STG_W 4160          // word offset of stage
#define SMEM_WORDS (SW_STG_W + ROWS * SPW)
#define DSMEM_BYTES (SMEM_WORDS * 4)

__device__ __forceinline__ float sigf(float x) { return 1.0f / (1.0f + expf(-x)); }

__device__ __forceinline__ void cpa16s(unsigned* sm, const void* gm) {
    unsigned sa = (unsigned)__cvta_generic_to_shared(sm);
    asm volatile("cp.async.cg.shared.global [%0], [%1], 16;" :: "r"(sa), "l"(gm) : "memory");
}
#define CP_COMMIT() asm volatile("cp.async.commit_group;" ::: "memory")
#define CP_WAIT(n)  asm volatile("cp.async.wait_group %0;" :: "n"(n) : "memory")

__device__ __forceinline__ unsigned long long dup2(float x) {
    unsigned long long r; unsigned u = __float_as_uint(x);
    asm("mov.b64 %0, {%1, %1};" : "=l"(r) : "r"(u));
    return r;
}
__device__ __forceinline__ void fma2(unsigned long long& s, unsigned long long a, unsigned long long w) {
    asm("fma.rn.f32x2 %0, %1, %2, %0;" : "+l"(s) : "l"(a), "l"(w));
}
__device__ __forceinline__ void unpack2(unsigned long long s, float& x, float& y) {
    unsigned lo, hi; asm("mov.b64 {%0, %1}, %2;" : "=r"(lo), "=r"(hi) : "l"(s));
    x = __uint_as_float(lo); y = __uint_as_float(hi);
}
__device__ __forceinline__ unsigned char f2fp8(float x) {
    return (unsigned char)__nv_cvt_float_to_fp8(x, __NV_SATFINITE, __NV_E4M3);
}
__device__ __forceinline__ unsigned pk8x4(const float* p, float s0, float& sum) {
    float4 v = *(const float4*)p;
    sum += (v.x + v.y) + (v.z + v.w);
    unsigned short lo = __nv_cvt_float2_to_fp8x2(make_float2(v.x * SCA, v.y * SCA), __NV_SATFINITE, __NV_E4M3);
    unsigned short hi = __nv_cvt_float2_to_fp8x2(make_float2(v.z * SCA, v.w * SCA), __NV_SATFINITE, __NV_E4M3);
    return (unsigned)lo | ((unsigned)hi << 16);
}

// per-batch barrier (R7-R15 proven), GRP CTAs per batch
__device__ __forceinline__ void batchbar(int b) {
    __threadfence();
    __syncthreads();
    if (threadIdx.x == 0) {
        unsigned gen = g_bgen[b * 32];
        if (atomicAdd(&g_bcnt[b * 32], 1) == GRP - 1) {
            g_bcnt[b * 32] = 0;
            __threadfence();
            g_bgen[b * 32] = gen + 1;
        } else {
            while (g_bgen[b * 32] == gen) __nanosleep(32);
        }
        __threadfence();
    }
    __syncthreads();
}

// ---------- fp8 GEMM phase (C=16): acc[64 rows x 16]; warp w owns rows w*16..+15 ----------
// X^T fp8 loaded whole into smem; A streamed via LDG.128 from fragment-ordered
// fp8 pack (depth-4 ring over 32 k32-steps). mma m16n8k32 e4m3 (R10-proven).
__device__ void gemmF(const uint4* __restrict__ Apk,
                      const unsigned char* __restrict__ Xb,
                      unsigned* smem_u, float acc[2][4]) {
    const int tid = threadIdx.x, w = tid >> 5, lane = tid & 31;

    __syncthreads();               // prior phase finished reading smem
#pragma unroll
    for (int q = 0; q < 8; q++) {
        int i = tid + q * NTHR;
        int c = i >> 6, ch = i & 63;
        cpa16s(smem_u + (c * XPB + ch * 16) / 4, Xb + (size_t)c * NN + ch * 16);
    }
    CP_COMMIT();
    CP_WAIT(0);
    __syncthreads();

#pragma unroll
    for (int nt = 0; nt < 2; nt++)
#pragma unroll
        for (int q = 0; q < 4; q++) acc[nt][q] = 0.f;

    const unsigned xB = (unsigned)__cvta_generic_to_shared(smem_u);
    const unsigned bbase = xB + (unsigned)(lane >> 2) * XPB + (unsigned)(lane & 3) * 4;
    const uint4* Aw = Apk + (size_t)w * 32 * 32 + lane;

    uint4 r0[4];
#pragma unroll
    for (int p = 0; p < 4; p++) r0[p] = Aw[p * 32];

    for (int kb = 0; kb < 8; kb++) {
#pragma unroll
        for (int q = 0; q < 4; q++) {
            const int ks = kb * 4 + q;
            unsigned bf[2][2];
#pragma unroll
            for (int nt = 0; nt < 2; nt++) {
                unsigned ad = bbase + (unsigned)nt * 8 * XPB + (unsigned)ks * 32;
                asm volatile("ld.shared.b32 %0, [%1];" : "=r"(bf[nt][0]) : "r"(ad));
                asm volatile("ld.shared.b32 %0, [%1];" : "=r"(bf[nt][1]) : "r"(ad + 16));
            }
            uint4 fa = r0[q];
            if (kb < 7) r0[q] = Aw[(ks + 4) * 32];
#pragma unroll
            for (int nt = 0; nt < 2; nt++) {
                asm volatile(
                    "mma.sync.aligned.m16n8k32.row.col.f32.e4m3.e4m3.f32 "
                    "{%0,%1,%2,%3},{%4,%5,%6,%7},{%8,%9},{%0,%1,%2,%3};"
                    : "+f"(acc[nt][0]), "+f"(acc[nt][1]), "+f"(acc[nt][2]), "+f"(acc[nt][3])
                    : "r"(fa.x), "r"(fa.y), "r"(fa.z), "r"(fa.w),
                      "r"(bf[nt][0]), "r"(bf[nt][1]));
            }
        }
    }
}

// scatter acc (unscaled by OSC) to stage (64 rows, pitch 17); caller reads rows
__device__ __forceinline__ void toStage(unsigned* smem_u, const float acc[2][4]) {
    float* stage = (float*)(smem_u + SW_STG_W);
    const int tid = threadIdx.x, w = tid >> 5, lane = tid & 31;
    const int g = lane >> 2, c2 = (lane & 3) * 2;
    const int rr = w * 16 + g;
#pragma unroll
    for (int nt = 0; nt < 2; nt++) {
        int col = nt * 8 + c2;
        stage[rr * SPW + col]           = acc[nt][0] * OSC;
        stage[rr * SPW + col + 1]       = acc[nt][1] * OSC;
        stage[(rr + 8) * SPW + col]     = acc[nt][2] * OSC;
        stage[(rr + 8) * SPW + col + 1] = acc[nt][3] * OSC;
    }
    __syncthreads();
}

// ================= persistent kernel =================
__global__ void __launch_bounds__(NTHR, 4) persistK(
    const float* __restrict__ A, const float* __restrict__ recent,
    const float* __restrict__ g1rW, const float* __restrict__ g1rb,
    const float* __restrict__ g1uW, const float* __restrict__ g1ub,
    const float* __restrict__ g1cW, const float* __restrict__ g1cb,
    const float* __restrict__ g2rW, const float* __restrict__ g2rb,
    const float* __restrict__ g2uW, const float* __restrict__ g2ub,
    const float* __restrict__ g2cW, const float* __restrict__ g2cb,
    const float* __restrict__ gcnW, const float* __restrict__ gcnb,
    float* __restrict__ out) {
    extern __shared__ __align__(16) unsigned smem_u[];
    __shared__ __align__(16) float tabs[2530];
    float* stage = (float*)(smem_u + SW_STG_W);

    const int tid = threadIdx.x, w = tid >> 5, lane = tid & 31;
    const int b = blockIdx.x >> 4, rb = blockIdx.x & 15;
    const int row0 = rb * ROWS;
    const int row = tid & 63, jh = tid >> 6, j0 = jh * 8;
    const int n0 = row0 + row;
    const size_t r0 = (size_t)b * NN + n0;

    // ---- weight tables into static smem ----
    {
        float2* W1 = (float2*)(tabs + 0);
        for (int i = tid; i < 288; i += NTHR) W1[i] = make_float2(g1rW[i], g1uW[i]);
        float2* W2 = (float2*)(tabs + 576);
        for (int i = tid; i < 512; i += NTHR) W2[i] = make_float2(g2rW[i], g2uW[i]);
        float2* C1 = (float2*)(tabs + 1600);
        for (int i = tid; i < 144; i += NTHR) {
            int k = i >> 3, m = i & 7;
            C1[i] = make_float2(g1cW[(2 * m) * 18 + k], g1cW[(2 * m + 1) * 18 + k]);
        }
        float2* C2 = (float2*)(tabs + 1888);
        for (int i = tid; i < 256; i += NTHR) {
            int k = i >> 3, m = i & 7;
            C2[i] = make_float2(g2cW[(2 * m) * 32 + k], g2cW[(2 * m + 1) * 32 + k]);
        }
        if (tid < 16) ((float2*)(tabs + 2400))[tid] = make_float2(g1rb[tid], g1ub[tid]);
        else if (tid < 32) ((float2*)(tabs + 2432))[tid - 16] = make_float2(g2rb[tid - 16], g2ub[tid - 16]);
        else if (tid < 40) ((float2*)(tabs + 2464))[tid - 32] = make_float2(g1cb[2 * (tid - 32)], g1cb[2 * (tid - 32) + 1]);
        else if (tid < 48) ((float2*)(tabs + 2480))[tid - 40] = make_float2(g2cb[2 * (tid - 40)], g2cb[2 * (tid - 40) + 1]);
        else if (tid < 80) { int i = tid - 48; tabs[2496 + i] = gcnW[(i >> 4) * 80 + (i & 15)]; }
        else if (tid < 82) tabs[2528 + tid - 80] = gcnb[tid - 80];
    }

    // ---- pack own A slice (64 rows) into e4m3 mma-fragment order + fused rowsum ----
    const float* Arow = A + ((size_t)b * NN + row0) * NN;
    uint4* pk = d_Apk + (size_t)blockIdx.x * 4096;
    {
        const int gr = lane >> 2, k0b = (lane & 3) * 4;
        const int blk = w;                           // 4 warps, 4 blocks
        const int rowbase = blk * 16;
        const float* rp0 = Arow + (size_t)(rowbase + gr) * NN;
        const float* rp8 = Arow + (size_t)(rowbase + gr + 8) * NN;
        float s0 = 0.f, s8 = 0.f;
        for (int ks = 0; ks < 32; ks++) {
            int k0 = ks * 32 + k0b;
            uint4 u;
            u.x = pk8x4(rp0 + k0, 0.f, s0);
            u.y = pk8x4(rp8 + k0, 0.f, s8);
            u.z = pk8x4(rp0 + k0 + 16, 0.f, s0);
            u.w = pk8x4(rp8 + k0 + 16, 0.f, s8);
            pk[((size_t)blk * 32 + ks) * 32 + lane] = u;
        }
#pragma unroll
        for (int o = 1; o < 4; o <<= 1) {
            s0 += __shfl_xor_sync(~0u, s0, o);
            s8 += __shfl_xor_sync(~0u, s8, o);
        }
        if ((lane & 3) == 0) {
            d_scratch[OFF_RS + (size_t)b * NN + row0 + rowbase + gr]     = s0;
            d_scratch[OFF_RS + (size_t)b * NN + row0 + rowbase + gr + 8] = s8;
        }
    }

    // ---- gather x_t (transposed fp8, x SCX; t-range split by jh) + zero h columns ----
    {
        const float2* rp = (const float2*)recent;
        for (int t = jh * 12; t < jh * 12 + 12; t++) {
            float2 v = rp[(size_t)(b * TT + t) * NN + n0];
            d_xt[((size_t)b * 48 + 2 * t) * NN + n0]     = f2fp8(v.x * SCX);
            d_xt[((size_t)b * 48 + 2 * t + 1) * NN + n0] = f2fp8(v.y * SCX);
        }
        for (int c = jh * 16; c < jh * 16 + 16; c++) d_xbf[((size_t)b * 48 + c) * NN + n0] = 0;
    }

    float h1[8], h2[8], uu[8], ah1[16], ah2[16];
#pragma unroll
    for (int k = 0; k < 8; k++) { h1[k] = 0.f; h2[k] = 0.f; }
#pragma unroll
    for (int k = 0; k < 16; k++) { ah1[k] = 0.f; ah2[k] = 0.f; }
    float acc[2][4];

    batchbar(b);

    // ---- A @ x_t for all 24 timesteps (CTA-local outputs) ----
    for (int g = 0; g < 3; g++) {
        gemmF(pk, d_xt + ((size_t)b * 48 + g * 16) * NN, smem_u, acc);
        toStage(smem_u, acc);
        float* axp = d_scratch + OFF_AX + (size_t)g * (BB * NN * 16) + r0 * 16 + jh * 8;
        const float* srow = stage + row * SPW + jh * 8;
        ((float4*)axp)[0] = make_float4(srow[0], srow[1], srow[2], srow[3]);
        ((float4*)axp)[1] = make_float4(srow[4], srow[5], srow[6], srow[7]);
    }

    const unsigned char* xbB = d_xbf + (size_t)b * 48 * NN;
    unsigned char* xo_h1 = d_xbf + ((size_t)b * 48 + 0) * NN + n0;
    unsigned char* xo_h2 = d_xbf + ((size_t)b * 48 + 16) * NN + n0;
    unsigned char* xo_rh = d_xbf + ((size_t)b * 48 + 32) * NN + n0;

    const unsigned long long* W1ru = (const unsigned long long*)(tabs + 0);
    const unsigned long long* W2ru = (const unsigned long long*)(tabs + 576);
    const unsigned long long* W1cp = (const unsigned long long*)(tabs + 1600);
    const unsigned long long* W2cp = (const unsigned long long*)(tabs + 1888);
    const unsigned long long* B1ru = (const unsigned long long*)(tabs + 2400);
    const unsigned long long* B2ru = (const unsigned long long*)(tabs + 2432);
    const unsigned long long* B1cp = (const unsigned long long*)(tabs + 2464);
    const unsigned long long* B2cp = (const unsigned long long*)(tabs + 2480);

    for (int t = 0; t < TT; t++) {
        const int g = t >> 3, p = t & 7;
        const float* axp = d_scratch + OFF_AX + (size_t)g * (BB * NN * 16) + r0 * 16 + p * 2;
        float2 axv = *(const float2*)axp;

        // ---- gates1: [ax | ah1(regs)] -> uu, r1*h1 (no gemm) ----
        {
            float xh[18];
            xh[0] = axv.x; xh[1] = axv.y;
#pragma unroll
            for (int k = 0; k < 16; k++) xh[2 + k] = ah1[k];
#pragma unroll
            for (int jj = 0; jj < 8; jj++) {
                const int j = j0 + jj;
                unsigned long long s = B1ru[j];
#pragma unroll
                for (int k = 0; k < 18; k++) fma2(s, dup2(xh[k]), W1ru[j * 18 + k]);
                float sr, su; unpack2(s, sr, su);
                uu[jj] = sigf(su);
                xo_rh[(size_t)j * NN] = f2fp8(sigf(sr) * h1[jj] * SCX);
            }
        }
        batchbar(b);

        // ---- G1: A@(r1*h1); gates2 -> h1' ----
        {
            gemmF(pk, xbB + (size_t)32 * NN, smem_u, acc);
            toStage(smem_u, acc);
            const float* srow = stage + row * SPW;
            float xh[18];
            xh[0] = axv.x; xh[1] = axv.y;
#pragma unroll
            for (int k = 0; k < 16; k++) xh[2 + k] = srow[k];
            unsigned long long sm[4];
#pragma unroll
            for (int m = 0; m < 4; m++) sm[m] = B1cp[jh * 4 + m];
#pragma unroll
            for (int k = 0; k < 18; k++) {
                unsigned long long a = dup2(xh[k]);
#pragma unroll
                for (int m = 0; m < 4; m++) fma2(sm[m], a, W1cp[k * 8 + jh * 4 + m]);
            }
#pragma unroll
            for (int m = 0; m < 4; m++) {
                float c0, c1; unpack2(sm[m], c0, c1);
                int jj = 2 * m;
                h1[jj]     = uu[jj]     * h1[jj]     + (1.f - uu[jj])     * tanhf(c0);
                h1[jj + 1] = uu[jj + 1] * h1[jj + 1] + (1.f - uu[jj + 1]) * tanhf(c1);
                xo_h1[(size_t)(j0 + jj) * NN]     = f2fp8(h1[jj] * SCX);
                xo_h1[(size_t)(j0 + jj + 1) * NN] = f2fp8(h1[jj + 1] * SCX);
            }
        }
        batchbar(b);

        // ---- G2: A@h1' -> ah1 (persist); gates3 -> uu, r2*h2 ----
        {
            gemmF(pk, xbB, smem_u, acc);
            toStage(smem_u, acc);
            const float* srow = stage + row * SPW;
#pragma unroll
            for (int k = 0; k < 16; k++) ah1[k] = srow[k];
#pragma unroll
            for (int jj = 0; jj < 8; jj++) {
                const int j = j0 + jj;
                unsigned long long s = B2ru[j];
#pragma unroll
                for (int k = 0; k < 16; k++) fma2(s, dup2(ah1[k]), W2ru[j * 32 + k]);
#pragma unroll
                for (int k = 0; k < 16; k++) fma2(s, dup2(ah2[k]), W2ru[j * 32 + 16 + k]);
                float sr, su; unpack2(s, sr, su);
                uu[jj] = sigf(su);
                xo_rh[(size_t)j * NN] = f2fp8(sigf(sr) * h2[jj] * SCX);
            }
        }
        batchbar(b);

        // ---- G3: A@(r2*h2); gates4 -> h2' ----
        {
            gemmF(pk, xbB + (size_t)32 * NN, smem_u, acc);
            toStage(smem_u, acc);
            const float* srow = stage + row * SPW;
            unsigned long long sm[4];
#pragma unroll
            for (int m = 0; m < 4; m++) sm[m] = B2cp[jh * 4 + m];
#pragma unroll
            for (int k = 0; k < 16; k++) {
                unsigned long long a = dup2(ah1[k]);
#pragma unroll
                for (int m = 0; m < 4; m++) fma2(sm[m], a, W2cp[k * 8 + jh * 4 + m]);
            }
#pragma unroll
            for (int k = 0; k < 16; k++) {
                unsigned long long a = dup2(srow[k]);
#pragma unroll
                for (int m = 0; m < 4; m++) fma2(sm[m], a, W2cp[(16 + k) * 8 + jh * 4 + m]);
            }
#pragma unroll
            for (int m = 0; m < 4; m++) {
                float c0, c1; unpack2(sm[m], c0, c1);
                int jj = 2 * m;
                h2[jj]     = uu[jj]     * h2[jj]     + (1.f - uu[jj])     * tanhf(c0);
                h2[jj + 1] = uu[jj + 1] * h2[jj + 1] + (1.f - uu[jj + 1]) * tanhf(c1);
                xo_h2[(size_t)(j0 + jj) * NN]     = f2fp8(h2[jj] * SCX);
                xo_h2[(size_t)(j0 + jj + 1) * NN] = f2fp8(h2[jj + 1] * SCX);
            }
        }
        batchbar(b);

        // ---- G4: A@h2' -> ah2 (persist; feeds next gates3 + final GCN) ----
        gemmF(pk, xbB + (size_t)16 * NN, smem_u, acc);
        toStage(smem_u, acc);
        {
            const float* srow = stage + row * SPW;
#pragma unroll
            for (int k = 0; k < 16; k++) ah2[k] = srow[k];
        }
        // no barrier: next write (gates1 -> rh cols 32-47) doesn't alias cols 16-31,
        // and the batchbar after gates1 precedes the next gemm read.
    }

    // ---- final: ah2 (= A@h2 final) + folded trend/feat, tanh ----
    if (jh == 0) {
        float rs = d_scratch[OFF_RS + r0];
        float o0 = tabs[2528] + rs * d_scratch[OFF_TVF + b * 2];
        float o1 = tabs[2529] + rs * d_scratch[OFF_TVF + b * 2 + 1];
#pragma unroll
        for (int c = 0; c < 16; c++) {
            o0 += ah2[c] * tabs[2496 + c];
            o1 += ah2[c] * tabs[2496 + 16 + c];
        }
        *(float2*)(out + r0 * 2) = make_float2(tanhf(o0), tanhf(o1));
    }
}

// ---- 2-layer LSTM + feat FF folded into tvf (B,2) ----
__global__ __launch_bounds__(1024) void prepK(
    const float* __restrict__ trend, const float* __restrict__ tf,
    const float* __restrict__ Wih0, const float* __restrict__ Whh0,
    const float* __restrict__ bih0, const float* __restrict__ bhh0,
    const float* __restrict__ Wih1, const float* __restrict__ Whh1,
    const float* __restrict__ bih1, const float* __restrict__ bhh1,
    const float* __restrict__ ffW, const float* __restrict__ ffb,
    const float* __restrict__ gcnW) {
    __shared__ float h1s[32][32], c1s[32][32], h2s[32][32], c2s[32][32], feats[32][32];
    int tid = threadIdx.x;
    int b = tid >> 5, j = tid & 31;
    h1s[b][j] = 0.f; c1s[b][j] = 0.f; h2s[b][j] = 0.f; c2s[b][j] = 0.f;
    __syncthreads();

    for (int t = 0; t < TT; t++) {
        float x0 = trend[(b * TT + t) * 2 + 0];
        float x1 = trend[(b * TT + t) * 2 + 1];
        float g0[4];
#pragma unroll
        for (int g = 0; g < 4; g++) {
            int idx = g * 32 + j;
            float s = bih0[idx] + bhh0[idx] + Wih0[idx * 2] * x0 + Wih0[idx * 2 + 1] * x1;
            for (int k = 0; k < 32; k++) s += Whh0[idx * 32 + k] * h1s[b][k];
            g0[g] = s;
        }
        float c1 = sigf(g0[1]) * c1s[b][j] + sigf(g0[0]) * tanhf(g0[2]);
        float h1 = sigf(g0[3]) * tanhf(c1);
        __syncthreads();
        h1s[b][j] = h1; c1s[b][j] = c1;
        __syncthreads();

        float g1[4];
#pragma unroll
        for (int g = 0; g < 4; g++) {
            int idx = g * 32 + j;
            float s = bih1[idx] + bhh1[idx];
            for (int k = 0; k < 32; k++)
                s += Wih1[idx * 32 + k] * h1s[b][k] + Whh1[idx * 32 + k] * h2s[b][k];
            g1[g] = s;
        }
        float c2 = sigf(g1[1]) * c2s[b][j] + sigf(g1[0]) * tanhf(g1[2]);
        float h2 = sigf(g1[3]) * tanhf(c2);
        __syncthreads();
        h2s[b][j] = h2; c2s[b][j] = c2;
        __syncthreads();
    }

    float s = ffb[j];
    for (int k = 0; k < 31; k++) s += tf[b * 31 + k] * ffW[j * 31 + k];
    feats[b][j] = fmaxf(s, 0.f);
    __syncthreads();

    if (tid < 64) {
        int bb = tid >> 1, f = tid & 1;
        float s2 = 0.f;
        for (int c = 0; c < 32; c++)
            s2 += h2s[bb][c] * gcnW[f * 80 + 16 + c] + feats[bb][c] * gcnW[f * 80 + 48 + c];
        d_scratch[OFF_TVF + bb * 2 + f] = s2;
    }
}

// ================================== launcher ===================================
extern "C" void kernel_launch(void* const* d_in, const int* in_sizes, int n_in,
                              void* d_out, int out_size) {
    const float* recent = (const float*)d_in[0];
    const float* trend  = (const float*)d_in[1];
    const float* A      = (const float*)d_in[2];
    const float* tf     = (const float*)d_in[3];
    const float* g1rW = (const float*)d_in[4],  *g1rb = (const float*)d_in[5];
    const float* g1uW = (const float*)d_in[6],  *g1ub = (const float*)d_in[7];
    const float* g1cW = (const float*)d_in[8],  *g1cb = (const float*)d_in[9];
    const float* g2rW = (const float*)d_in[10], *g2rb = (const float*)d_in[11];
    const float* g2uW = (const float*)d_in[12], *g2ub = (const float*)d_in[13];
    const float* g2cW = (const float*)d_in[14], *g2cb = (const float*)d_in[15];
    const float* Wih0 = (const float*)d_in[16], *Whh0 = (const float*)d_in[17];
    const float* bih0 = (const float*)d_in[18], *bhh0 = (const float*)d_in[19];
    const float* Wih1 = (const float*)d_in[20], *Whh1 = (const float*)d_in[21];
    const float* bih1 = (const float*)d_in[22], *bhh1 = (const float*)d_in[23];
    const float* ffW  = (const float*)d_in[24], *ffb  = (const float*)d_in[25];
    const float* gcnW = (const float*)d_in[26], *gcnb = (const float*)d_in[27];
    float* out = (float*)d_out;

    cudaFuncSetAttribute(persistK, cudaFuncAttributeMaxDynamicSharedMemorySize, DSMEM_BYTES);

    prepK<<<1, 1024>>>(trend, tf, Wih0, Whh0, bih0, bhh0,
                       Wih1, Whh1, bih1, bhh1, ffW, ffb, gcnW);
    persistK<<<NCTA, NTHR, DSMEM_BYTES>>>(A, recent,
                                          g1rW, g1rb, g1uW, g1ub, g1cW, g1cb,
                                          g2rW, g2rb, g2uW, g2ub, g2cW, g2cb,
                                          gcnW, gcnb, out);
}

// round 17
// speedup vs baseline: 1.0244x; 1.0053x over previous
#include <cuda_runtime.h>
#include <cuda_bf16.h>
#include <cuda_fp8.h>
#include <math.h>

#define BB 32
#define TT 24
#define NN 1024
#define NCTA 256
#define NTHR 128
#define GRP 8                  // CTAs per batch == cluster size
#define ROWS 128               // rows per CTA

#define SCA 131072.f           // A scale (2^17)
#define SCX 16.f               // X scale (2^4)
#define OSC (1.f / 2097152.f)  // output unscale (2^-21)

// ---------------- fp32 scratch ----------------
#define OFF_AX   0                          // 3 groups x (B,N,16) = A@x_t
#define OFF_RS   (3 * BB * NN * 16)         // (B,N) rowsum(A)
#define OFF_TVF  (OFF_RS + BB * NN)         // (B,2)
#define SCRATCH_FLOATS (OFF_TVF + BB * 2)

__device__ float d_scratch[SCRATCH_FLOATS];
// A e4m3 packed in mma-fragment order: per CTA 8192 uint4 (128KB)
// index: ((blk*32 + ks)*32 + lane), blk = 16-row block 0..7, ks = k32 step
__device__ uint4 d_Apk[(size_t)NCTA * 8192];
__device__ unsigned char d_xbf[(size_t)BB * 48 * NN];   // X^T fp8: 0-15 h1, 16-31 h2, 32-47 r*h
__device__ unsigned char d_xt [(size_t)BB * 48 * NN];   // gathered x_t fp8, transposed

// dynamic smem: X fp8 16 x 1040 B | stage 128 x 17 fp32
#define XPB 1040
#define SPW 17
#define SW_STG_W 4160          // word offset of stage
#define SMEM_WORDS (SW_STG_W + ROWS * SPW)
#define DSMEM_BYTES (SMEM_WORDS * 4)

__device__ __forceinline__ float sigf(float x) { return 1.0f / (1.0f + expf(-x)); }

__device__ __forceinline__ void cpa16s(unsigned* sm, const void* gm) {
    unsigned sa = (unsigned)__cvta_generic_to_shared(sm);
    asm volatile("cp.async.cg.shared.global [%0], [%1], 16;" :: "r"(sa), "l"(gm) : "memory");
}
#define CP_COMMIT() asm volatile("cp.async.commit_group;" ::: "memory")
#define CP_WAIT(n)  asm volatile("cp.async.wait_group %0;" :: "n"(n) : "memory")

__device__ __forceinline__ unsigned long long dup2(float x) {
    unsigned long long r; unsigned u = __float_as_uint(x);
    asm("mov.b64 %0, {%1, %1};" : "=l"(r) : "r"(u));
    return r;
}
__device__ __forceinline__ void fma2(unsigned long long& s, unsigned long long a, unsigned long long w) {
    asm("fma.rn.f32x2 %0, %1, %2, %0;" : "+l"(s) : "l"(a), "l"(w));
}
__device__ __forceinline__ void unpack2(unsigned long long s, float& x, float& y) {
    unsigned lo, hi; asm("mov.b64 {%0, %1}, %2;" : "=r"(lo), "=r"(hi) : "l"(s));
    x = __uint_as_float(lo); y = __uint_as_float(hi);
}
__device__ __forceinline__ unsigned char f2fp8(float x) {
    return (unsigned char)__nv_cvt_float_to_fp8(x, __NV_SATFINITE, __NV_E4M3);
}
__device__ __forceinline__ unsigned pk8x4(const float* p, float& sum) {
    float4 v = *(const float4*)p;
    sum += (v.x + v.y) + (v.z + v.w);
    unsigned short lo = __nv_cvt_float2_to_fp8x2(make_float2(v.x * SCA, v.y * SCA), __NV_SATFINITE, __NV_E4M3);
    unsigned short hi = __nv_cvt_float2_to_fp8x2(make_float2(v.z * SCA, v.w * SCA), __NV_SATFINITE, __NV_E4M3);
    return (unsigned)lo | ((unsigned)hi << 16);
}

// hardware cluster barrier: arrive has release, wait has acquire semantics at
// cluster scope -> orders the batch's global X writes before the next gemm's
// reads (both observer threads are inside the cluster). ~380 cyc total.
__device__ __forceinline__ void batchbar() {
    asm volatile("barrier.cluster.arrive.aligned;" ::: "memory");
    asm volatile("barrier.cluster.wait.aligned;" ::: "memory");
}

// ---------- fp8 GEMM phase (C=16): acc[128 rows x 16]; warp w owns rows w*32..+31 ----------
// X^T fp8 loaded whole into smem; A streamed via LDG.128 from fragment-ordered
// fp8 pack (depth-4 ring per m-block). mma m16n8k32 e4m3 (R10/R16-proven).
__device__ void gemmF(const uint4* __restrict__ Apk,
                      const unsigned char* __restrict__ Xb,
                      unsigned* smem_u, float acc[2][2][4]) {
    const int tid = threadIdx.x, w = tid >> 5, lane = tid & 31;

    __syncthreads();               // prior phase finished reading smem
#pragma unroll
    for (int q = 0; q < 8; q++) {
        int i = tid + q * NTHR;
        int c = i >> 6, ch = i & 63;
        cpa16s(smem_u + (c * XPB + ch * 16) / 4, Xb + (size_t)c * NN + ch * 16);
    }
    CP_COMMIT();
    CP_WAIT(0);
    __syncthreads();

#pragma unroll
    for (int mt = 0; mt < 2; mt++)
#pragma unroll
        for (int nt = 0; nt < 2; nt++)
#pragma unroll
            for (int q = 0; q < 4; q++) acc[mt][nt][q] = 0.f;

    const unsigned xB = (unsigned)__cvta_generic_to_shared(smem_u);
    const unsigned bbase = xB + (unsigned)(lane >> 2) * XPB + (unsigned)(lane & 3) * 4;
    const uint4* Aw0 = Apk + (size_t)(w * 2) * 1024 + lane;   // blk = 2w
    const uint4* Aw1 = Aw0 + 1024;                             // blk = 2w+1

    uint4 r0[4], r1[4];
#pragma unroll
    for (int p = 0; p < 4; p++) { r0[p] = Aw0[p * 32]; r1[p] = Aw1[p * 32]; }

    for (int kb = 0; kb < 8; kb++) {
#pragma unroll
        for (int q = 0; q < 4; q++) {
            const int ks = kb * 4 + q;
            unsigned bf[2][2];
#pragma unroll
            for (int nt = 0; nt < 2; nt++) {
                unsigned ad = bbase + (unsigned)nt * 8 * XPB + (unsigned)ks * 32;
                asm volatile("ld.shared.b32 %0, [%1];" : "=r"(bf[nt][0]) : "r"(ad));
                asm volatile("ld.shared.b32 %0, [%1];" : "=r"(bf[nt][1]) : "r"(ad + 16));
            }
            uint4 fa0 = r0[q], fa1 = r1[q];
            if (kb < 7) {
                r0[q] = Aw0[(ks + 4) * 32];
                r1[q] = Aw1[(ks + 4) * 32];
            }
#pragma unroll
            for (int nt = 0; nt < 2; nt++) {
                asm volatile(
                    "mma.sync.aligned.m16n8k32.row.col.f32.e4m3.e4m3.f32 "
                    "{%0,%1,%2,%3},{%4,%5,%6,%7},{%8,%9},{%0,%1,%2,%3};"
                    : "+f"(acc[0][nt][0]), "+f"(acc[0][nt][1]),
                      "+f"(acc[0][nt][2]), "+f"(acc[0][nt][3])
                    : "r"(fa0.x), "r"(fa0.y), "r"(fa0.z), "r"(fa0.w),
                      "r"(bf[nt][0]), "r"(bf[nt][1]));
                asm volatile(
                    "mma.sync.aligned.m16n8k32.row.col.f32.e4m3.e4m3.f32 "
                    "{%0,%1,%2,%3},{%4,%5,%6,%7},{%8,%9},{%0,%1,%2,%3};"
                    : "+f"(acc[1][nt][0]), "+f"(acc[1][nt][1]),
                      "+f"(acc[1][nt][2]), "+f"(acc[1][nt][3])
                    : "r"(fa1.x), "r"(fa1.y), "r"(fa1.z), "r"(fa1.w),
                      "r"(bf[nt][0]), "r"(bf[nt][1]));
            }
        }
    }
}

// scatter acc (unscaled by OSC) to stage (128 rows, pitch 17), sync, read own row
__device__ __forceinline__ void toRows(unsigned* smem_u, const float acc[2][2][4], float* d) {
    float* stage = (float*)(smem_u + SW_STG_W);
    const int tid = threadIdx.x, w = tid >> 5, lane = tid & 31;
    const int g = lane >> 2, c2 = (lane & 3) * 2;
#pragma unroll
    for (int mt = 0; mt < 2; mt++) {
        int rr = w * 32 + mt * 16 + g;
#pragma unroll
        for (int nt = 0; nt < 2; nt++) {
            int col = nt * 8 + c2;
            stage[rr * SPW + col]           = acc[mt][nt][0] * OSC;
            stage[rr * SPW + col + 1]       = acc[mt][nt][1] * OSC;
            stage[(rr + 8) * SPW + col]     = acc[mt][nt][2] * OSC;
            stage[(rr + 8) * SPW + col + 1] = acc[mt][nt][3] * OSC;
        }
    }
    __syncthreads();
    const float* srow = stage + tid * SPW;
#pragma unroll
    for (int k = 0; k < 16; k++) d[k] = srow[k];
}

// ================= persistent kernel (cluster = batch) =================
__global__ void __launch_bounds__(NTHR, 2) __cluster_dims__(GRP, 1, 1) persistK(
    const float* __restrict__ A, const float* __restrict__ recent,
    const float* __restrict__ g1rW, const float* __restrict__ g1rb,
    const float* __restrict__ g1uW, const float* __restrict__ g1ub,
    const float* __restrict__ g1cW, const float* __restrict__ g1cb,
    const float* __restrict__ g2rW, const float* __restrict__ g2rb,
    const float* __restrict__ g2uW, const float* __restrict__ g2ub,
    const float* __restrict__ g2cW, const float* __restrict__ g2cb,
    const float* __restrict__ gcnW, const float* __restrict__ gcnb,
    float* __restrict__ out) {
    extern __shared__ __align__(16) unsigned smem_u[];
    __shared__ __align__(16) float tabs[2530];

    const int tid = threadIdx.x, w = tid >> 5, lane = tid & 31;
    const int b = blockIdx.x >> 3, rb = blockIdx.x & 7;
    const int row0 = rb * ROWS, n0 = row0 + tid;
    const size_t r0 = (size_t)b * NN + n0;

    // ---- weight tables into static smem ----
    {
        float2* W1 = (float2*)(tabs + 0);
        for (int i = tid; i < 288; i += NTHR) W1[i] = make_float2(g1rW[i], g1uW[i]);
        float2* W2 = (float2*)(tabs + 576);
        for (int i = tid; i < 512; i += NTHR) W2[i] = make_float2(g2rW[i], g2uW[i]);
        float2* C1 = (float2*)(tabs + 1600);
        for (int i = tid; i < 144; i += NTHR) {
            int k = i >> 3, m = i & 7;
            C1[i] = make_float2(g1cW[(2 * m) * 18 + k], g1cW[(2 * m + 1) * 18 + k]);
        }
        float2* C2 = (float2*)(tabs + 1888);
        for (int i = tid; i < 256; i += NTHR) {
            int k = i >> 3, m = i & 7;
            C2[i] = make_float2(g2cW[(2 * m) * 32 + k], g2cW[(2 * m + 1) * 32 + k]);
        }
        if (tid < 16) ((float2*)(tabs + 2400))[tid] = make_float2(g1rb[tid], g1ub[tid]);
        else if (tid < 32) ((float2*)(tabs + 2432))[tid - 16] = make_float2(g2rb[tid - 16], g2ub[tid - 16]);
        else if (tid < 40) ((float2*)(tabs + 2464))[tid - 32] = make_float2(g1cb[2 * (tid - 32)], g1cb[2 * (tid - 32) + 1]);
        else if (tid < 48) ((float2*)(tabs + 2480))[tid - 40] = make_float2(g2cb[2 * (tid - 40)], g2cb[2 * (tid - 40) + 1]);
        else if (tid < 80) { int i = tid - 48; tabs[2496 + i] = gcnW[(i >> 4) * 80 + (i & 15)]; }
        else if (tid < 82) tabs[2528 + tid - 80] = gcnb[tid - 80];
    }

    // ---- pack own A slice (128 rows) into e4m3 mma-fragment order + fused rowsum ----
    const float* Arow = A + ((size_t)b * NN + row0) * NN;
    uint4* pk = d_Apk + (size_t)blockIdx.x * 8192;
    {
        const int gr = lane >> 2, k0b = (lane & 3) * 4;
        for (int blk = w; blk < 8; blk += 4) {       // each warp packs 2 blocks
            const int rowbase = blk * 16;
            const float* rp0 = Arow + (size_t)(rowbase + gr) * NN;
            const float* rp8 = Arow + (size_t)(rowbase + gr + 8) * NN;
            float s0 = 0.f, s8 = 0.f;
            for (int ks = 0; ks < 32; ks++) {
                int k0 = ks * 32 + k0b;
                uint4 u;
                u.x = pk8x4(rp0 + k0, s0);
                u.y = pk8x4(rp8 + k0, s8);
                u.z = pk8x4(rp0 + k0 + 16, s0);
                u.w = pk8x4(rp8 + k0 + 16, s8);
                pk[((size_t)blk * 32 + ks) * 32 + lane] = u;
            }
#pragma unroll
            for (int o = 1; o < 4; o <<= 1) {
                s0 += __shfl_xor_sync(~0u, s0, o);
                s8 += __shfl_xor_sync(~0u, s8, o);
            }
            if ((lane & 3) == 0) {
                d_scratch[OFF_RS + (size_t)b * NN + row0 + rowbase + gr]     = s0;
                d_scratch[OFF_RS + (size_t)b * NN + row0 + rowbase + gr + 8] = s8;
            }
        }
    }

    // ---- gather x_t (transposed fp8, x SCX) + zero h columns ----
    {
        const float2* rp = (const float2*)recent;
        for (int t = 0; t < TT; t++) {
            float2 v = rp[(size_t)(b * TT + t) * NN + n0];
            d_xt[((size_t)b * 48 + 2 * t) * NN + n0]     = f2fp8(v.x * SCX);
            d_xt[((size_t)b * 48 + 2 * t + 1) * NN + n0] = f2fp8(v.y * SCX);
        }
        for (int c = 0; c < 32; c++) d_xbf[((size_t)b * 48 + c) * NN + n0] = 0;
    }

    // per-thread recurrent state (1 thread = 1 row)
    float h1[16], h2[16], uu[16], ah1[16], ah2[16], d[16];
#pragma unroll
    for (int k = 0; k < 16; k++) { h1[k] = 0.f; h2[k] = 0.f; ah1[k] = 0.f; ah2[k] = 0.f; }
    float acc[2][2][4];

    batchbar();

    // ---- A @ x_t for all 24 timesteps (CTA-local outputs) ----
    for (int g = 0; g < 3; g++) {
        gemmF(pk, d_xt + ((size_t)b * 48 + g * 16) * NN, smem_u, acc);
        toRows(smem_u, acc, d);
        float* axp = d_scratch + OFF_AX + (size_t)g * (BB * NN * 16) + r0 * 16;
#pragma unroll
        for (int q = 0; q < 4; q++)
            ((float4*)axp)[q] = make_float4(d[4 * q], d[4 * q + 1], d[4 * q + 2], d[4 * q + 3]);
    }

    const unsigned char* xbB = d_xbf + (size_t)b * 48 * NN;
    unsigned char* xo_h1 = d_xbf + ((size_t)b * 48 + 0) * NN + n0;
    unsigned char* xo_h2 = d_xbf + ((size_t)b * 48 + 16) * NN + n0;
    unsigned char* xo_rh = d_xbf + ((size_t)b * 48 + 32) * NN + n0;

    const unsigned long long* W1ru = (const unsigned long long*)(tabs + 0);
    const unsigned long long* W2ru = (const unsigned long long*)(tabs + 576);
    const unsigned long long* W1cp = (const unsigned long long*)(tabs + 1600);
    const unsigned long long* W2cp = (const unsigned long long*)(tabs + 1888);
    const unsigned long long* B1ru = (const unsigned long long*)(tabs + 2400);
    const unsigned long long* B2ru = (const unsigned long long*)(tabs + 2432);
    const unsigned long long* B1cp = (const unsigned long long*)(tabs + 2464);
    const unsigned long long* B2cp = (const unsigned long long*)(tabs + 2480);

    for (int t = 0; t < TT; t++) {
        const int g = t >> 3, p = t & 7;
        const float* axp = d_scratch + OFF_AX + (size_t)g * (BB * NN * 16) + r0 * 16 + p * 2;
        float2 axv = *(const float2*)axp;

        // ---- gates1: [ax | ah1(regs)] -> uu, r1*h1 (no gemm) ----
        {
            float xh[18];
            xh[0] = axv.x; xh[1] = axv.y;
#pragma unroll
            for (int k = 0; k < 16; k++) xh[2 + k] = ah1[k];
#pragma unroll
            for (int j = 0; j < 16; j++) {
                unsigned long long s = B1ru[j];
#pragma unroll
                for (int k = 0; k < 18; k++) fma2(s, dup2(xh[k]), W1ru[j * 18 + k]);
                float sr, su; unpack2(s, sr, su);
                uu[j] = sigf(su);
                xo_rh[(size_t)j * NN] = f2fp8(sigf(sr) * h1[j] * SCX);
            }
        }
        batchbar();

        // ---- G1: A@(r1*h1); gates2 -> h1' ----
        {
            gemmF(pk, xbB + (size_t)32 * NN, smem_u, acc);
            toRows(smem_u, acc, d);
            float xh[18];
            xh[0] = axv.x; xh[1] = axv.y;
#pragma unroll
            for (int k = 0; k < 16; k++) xh[2 + k] = d[k];
            unsigned long long sm[8];
#pragma unroll
            for (int m = 0; m < 8; m++) sm[m] = B1cp[m];
#pragma unroll
            for (int k = 0; k < 18; k++) {
                unsigned long long a = dup2(xh[k]);
#pragma unroll
                for (int m = 0; m < 8; m++) fma2(sm[m], a, W1cp[k * 8 + m]);
            }
#pragma unroll
            for (int m = 0; m < 8; m++) {
                float c0, c1; unpack2(sm[m], c0, c1);
                int j = 2 * m;
                h1[j]     = uu[j]     * h1[j]     + (1.f - uu[j])     * tanhf(c0);
                h1[j + 1] = uu[j + 1] * h1[j + 1] + (1.f - uu[j + 1]) * tanhf(c1);
                xo_h1[(size_t)j * NN]       = f2fp8(h1[j] * SCX);
                xo_h1[(size_t)(j + 1) * NN] = f2fp8(h1[j + 1] * SCX);
            }
        }
        batchbar();

        // ---- G2: A@h1' -> ah1 (persist); gates3 -> uu, r2*h2 ----
        {
            gemmF(pk, xbB, smem_u, acc);
            toRows(smem_u, acc, ah1);
#pragma unroll
            for (int j = 0; j < 16; j++) {
                unsigned long long s = B2ru[j];
#pragma unroll
                for (int k = 0; k < 16; k++) fma2(s, dup2(ah1[k]), W2ru[j * 32 + k]);
#pragma unroll
                for (int k = 0; k < 16; k++) fma2(s, dup2(ah2[k]), W2ru[j * 32 + 16 + k]);
                float sr, su; unpack2(s, sr, su);
                uu[j] = sigf(su);
                xo_rh[(size_t)j * NN] = f2fp8(sigf(sr) * h2[j] * SCX);
            }
        }
        batchbar();

        // ---- G3: A@(r2*h2); gates4 -> h2' ----
        {
            gemmF(pk, xbB + (size_t)32 * NN, smem_u, acc);
            toRows(smem_u, acc, d);
            unsigned long long sm[8];
#pragma unroll
            for (int m = 0; m < 8; m++) sm[m] = B2cp[m];
#pragma unroll
            for (int k = 0; k < 16; k++) {
                unsigned long long a = dup2(ah1[k]);
#pragma unroll
                for (int m = 0; m < 8; m++) fma2(sm[m], a, W2cp[k * 8 + m]);
            }
#pragma unroll
            for (int k = 0; k < 16; k++) {
                unsigned long long a = dup2(d[k]);
#pragma unroll
                for (int m = 0; m < 8; m++) fma2(sm[m], a, W2cp[(16 + k) * 8 + m]);
            }
#pragma unroll
            for (int m = 0; m < 8; m++) {
                float c0, c1; unpack2(sm[m], c0, c1);
                int j = 2 * m;
                h2[j]     = uu[j]     * h2[j]     + (1.f - uu[j])     * tanhf(c0);
                h2[j + 1] = uu[j + 1] * h2[j + 1] + (1.f - uu[j + 1]) * tanhf(c1);
                xo_h2[(size_t)j * NN]       = f2fp8(h2[j] * SCX);
                xo_h2[(size_t)(j + 1) * NN] = f2fp8(h2[j + 1] * SCX);
            }
        }
        batchbar();

        // ---- G4: A@h2' -> ah2 (persist; feeds next gates3 + final GCN) ----
        gemmF(pk, xbB + (size_t)16 * NN, smem_u, acc);
        toRows(smem_u, acc, ah2);
        // no barrier: next write (gates1 -> rh cols 32-47) doesn't alias cols 16-31,
        // and the batchbar after gates1 precedes the next gemm read.
    }

    // ---- final: ah2 (= A@h2 final) + folded trend/feat, tanh ----
    {
        float rs = d_scratch[OFF_RS + r0];
        float o0 = tabs[2528] + rs * d_scratch[OFF_TVF + b * 2];
        float o1 = tabs[2529] + rs * d_scratch[OFF_TVF + b * 2 + 1];
#pragma unroll
        for (int c = 0; c < 16; c++) {
            o0 += ah2[c] * tabs[2496 + c];
            o1 += ah2[c] * tabs[2496 + 16 + c];
        }
        *(float2*)(out + r0 * 2) = make_float2(tanhf(o0), tanhf(o1));
    }
    batchbar();   // no CTA exits while peers may still read its cluster-visible data
}

// ---- 2-layer LSTM + feat FF folded into tvf (B,2) ----
__global__ __launch_bounds__(1024) void prepK(
    const float* __restrict__ trend, const float* __restrict__ tf,
    const float* __restrict__ Wih0, const float* __restrict__ Whh0,
    const float* __restrict__ bih0, const float* __restrict__ bhh0,
    const float* __restrict__ Wih1, const float* __restrict__ Whh1,
    const float* __restrict__ bih1, const float* __restrict__ bhh1,
    const float* __restrict__ ffW, const float* __restrict__ ffb,
    const float* __restrict__ gcnW) {
    __shared__ float h1s[32][32], c1s[32][32], h2s[32][32], c2s[32][32], feats[32][32];
    int tid = threadIdx.x;
    int b = tid >> 5, j = tid & 31;
    h1s[b][j] = 0.f; c1s[b][j] = 0.f; h2s[b][j] = 0.f; c2s[b][j] = 0.f;
    __syncthreads();

    for (int t = 0; t < TT; t++) {
        float x0 = trend[(b * TT + t) * 2 + 0];
        float x1 = trend[(b * TT + t) * 2 + 1];
        float g0[4];
#pragma unroll
        for (int g = 0; g < 4; g++) {
            int idx = g * 32 + j;
            float s = bih0[idx] + bhh0[idx] + Wih0[idx * 2] * x0 + Wih0[idx * 2 + 1] * x1;
            for (int k = 0; k < 32; k++) s += Whh0[idx * 32 + k] * h1s[b][k];
            g0[g] = s;
        }
        float c1 = sigf(g0[1]) * c1s[b][j] + sigf(g0[0]) * tanhf(g0[2]);
        float h1 = sigf(g0[3]) * tanhf(c1);
        __syncthreads();
        h1s[b][j] = h1; c1s[b][j] = c1;
        __syncthreads();

        float g1[4];
#pragma unroll
        for (int g = 0; g < 4; g++) {
            int idx = g * 32 + j;
            float s = bih1[idx] + bhh1[idx];
            for (int k = 0; k < 32; k++)
                s += Wih1[idx * 32 + k] * h1s[b][k] + Whh1[idx * 32 + k] * h2s[b][k];
            g1[g] = s;
        }
        float c2 = sigf(g1[1]) * c2s[b][j] + sigf(g1[0]) * tanhf(g1[2]);
        float h2 = sigf(g1[3]) * tanhf(c2);
        __syncthreads();
        h2s[b][j] = h2; c2s[b][j] = c2;
        __syncthreads();
    }

    float s = ffb[j];
    for (int k = 0; k < 31; k++) s += tf[b * 31 + k] * ffW[j * 31 + k];
    feats[b][j] = fmaxf(s, 0.f);
    __syncthreads();

    if (tid < 64) {
        int bb = tid >> 1, f = tid & 1;
        float s2 = 0.f;
        for (int c = 0; c < 32; c++)
            s2 += h2s[bb][c] * gcnW[f * 80 + 16 + c] + feats[bb][c] * gcnW[f * 80 + 48 + c];
        d_scratch[OFF_TVF + bb * 2 + f] = s2;
    }
}

// ================================== launcher ===================================
extern "C" void kernel_launch(void* const* d_in, const int* in_sizes, int n_in,
                              void* d_out, int out_size) {
    const float* recent = (const float*)d_in[0];
    const float* trend  = (const float*)d_in[1];
    const float* A      = (const float*)d_in[2];
    const float* tf     = (const float*)d_in[3];
    const float* g1rW = (const float*)d_in[4],  *g1rb = (const float*)d_in[5];
    const float* g1uW = (const float*)d_in[6],  *g1ub = (const float*)d_in[7];
    const float* g1cW = (const float*)d_in[8],  *g1cb = (const float*)d_in[9];
    const float* g2rW = (const float*)d_in[10], *g2rb = (const float*)d_in[11];
    const float* g2uW = (const float*)d_in[12], *g2ub = (const float*)d_in[13];
    const float* g2cW = (const float*)d_in[14], *g2cb = (const float*)d_in[15];
    const float* Wih0 = (const float*)d_in[16], *Whh0 = (const float*)d_in[17];
    const float* bih0 = (const float*)d_in[18], *bhh0 = (const float*)d_in[19];
    const float* Wih1 = (const float*)d_in[20], *Whh1 = (const float*)d_in[21];
    const float* bih1 = (const float*)d_in[22], *bhh1 = (const float*)d_in[23];
    const float* ffW  = (const float*)d_in[24], *ffb  = (const float*)d_in[25];
    const float* gcnW = (const float*)d_in[26], *gcnb = (const float*)d_in[27];
    float* out = (float*)d_out;

    cudaFuncSetAttribute(persistK, cudaFuncAttributeMaxDynamicSharedMemorySize, DSMEM_BYTES);

    prepK<<<1, 1024>>>(trend, tf, Wih0, Whh0, bih0, bhh0,
                       Wih1, Whh1, bih1, bhh1, ffW, ffb, gcnW);
    persistK<<<NCTA, NTHR, DSMEM_BYTES>>>(A, recent,
                                          g1rW, g1rb, g1uW, g1ub, g1cW, g1cb,
                                          g2rW, g2rb, g2uW, g2ub, g2cW, g2cb,
                                          gcnW, gcnb, out);
}